// round 14
// baseline (speedup 1.0000x reference)
#include <cuda_runtime.h>
#include <cuda_fp16.h>
#include <math_constants.h>

#define BATCH 4
#define SEQ   2048
#define DIM   1024

// Scratch (static device arrays: allocation-guard-safe)
__device__ __half d_Qh[BATCH * SEQ * DIM];
__device__ __half d_Kh[BATCH * SEQ * DIM];
__device__ __half d_Vh[BATCH * SEQ * DIM];
__device__ float  d_S[(size_t)BATCH * SEQ * SEQ];   // fp32 scores (pre-scaled by 1/32)
__device__ __half d_P[(size_t)BATCH * SEQ * SEQ];   // unnormalized probs (fp16)
__device__ float  d_inv[BATCH * SEQ];               // 1/rowsum for deferred normalize
__device__ __half d_xh[BATCH * SEQ * DIM];          // fp16 x
__device__ __half d_Wh[3][DIM * DIM];               // fp16 Wq/Wk/Wv

// ---------------------------------------------------------------------------
// FP16 mma.sync (m16n8k16, f32 acc) GEMM: block tile 128x128, BK=64,
// 4-stage depth-3 cp.async ring, fragment double-buffering, 1 CTA/SM.
// 512 threads = 16 warps (4x4), warp tile 32x32.
// ---------------------------------------------------------------------------

#define BK 64        // halves of K per stage (4 k16 sub-steps)
#define SA_ST 72     // 64 + 8 pad (halves): ldsm rows at banks 4r -> distinct
#define SB_ST 136    // 128 + 8 pad (halves) for [k][n] V tile
#define NSTG 4
#define STG_A (128 * SA_ST)      // halves per A (or NT-B) stage  (9216)
#define STG_BV (BK * SB_ST)      // halves per V stage            (8704)

#define SMEM_NT (NSTG * STG_A * 2 * 2)          // 147456 B
#define SMEM_PV (NSTG * (STG_A + STG_BV) * 2)   // 143360 B

__device__ __forceinline__ void mma_f16(float* d, const unsigned* a, const unsigned* b) {
    asm volatile(
        "mma.sync.aligned.m16n8k16.row.col.f32.f16.f16.f32 "
        "{%0,%1,%2,%3}, {%4,%5,%6,%7}, {%8,%9}, {%0,%1,%2,%3};\n"
        : "+f"(d[0]), "+f"(d[1]), "+f"(d[2]), "+f"(d[3])
        : "r"(a[0]), "r"(a[1]), "r"(a[2]), "r"(a[3]), "r"(b[0]), "r"(b[1]));
}

__device__ __forceinline__ void ldsm4(unsigned addr, unsigned r[4]) {
    asm volatile("ldmatrix.sync.aligned.m8n8.x4.shared.b16 {%0,%1,%2,%3}, [%4];"
                 : "=r"(r[0]), "=r"(r[1]), "=r"(r[2]), "=r"(r[3]) : "r"(addr));
}
__device__ __forceinline__ void ldsm4t(unsigned addr, unsigned r[4]) {
    asm volatile("ldmatrix.sync.aligned.m8n8.x4.trans.shared.b16 {%0,%1,%2,%3}, [%4];"
                 : "=r"(r[0]), "=r"(r[1]), "=r"(r[2]), "=r"(r[3]) : "r"(addr));
}

__device__ __forceinline__ void cp16(void* smem, const void* gmem) {
    unsigned s = (unsigned)__cvta_generic_to_shared(smem);
    asm volatile("cp.async.cg.shared.global [%0], [%1], 16;\n" :: "r"(s), "l"(gmem));
}
__device__ __forceinline__ void cp_commit() { asm volatile("cp.async.commit_group;\n"); }
__device__ __forceinline__ void cp_wait2()  { asm volatile("cp.async.wait_group 2;\n"); }

// 128x64h K-contiguous tile into smem [128][SA_ST] (2 cp16/thread @512 thr).
__device__ __forceinline__ void load_km(__half* s, const __half* g, int ld, int t) {
#pragma unroll
    for (int i = 0; i < 2; ++i) {
        const int cid = t + i * 512;       // 0..1023
        const int row = cid >> 3, ch = cid & 7;
        cp16(&s[row * SA_ST + ch * 8], g + (size_t)row * ld + ch * 8);
    }
}

// 64x128h [k][n] V tile into smem [64][SB_ST] (2 cp16/thread @512 thr).
__device__ __forceinline__ void load_nm(__half* s, const __half* g, int ld, int t) {
#pragma unroll
    for (int i = 0; i < 2; ++i) {
        const int cid = t + i * 512;
        const int row = cid >> 4, ch = cid & 15;
        cp16(&s[row * SB_ST + ch * 8], g + (size_t)row * ld + ch * 8);
    }
}

__device__ __forceinline__ void ldsmA(unsigned base, int kb, unsigned a[2][4]) {
#pragma unroll
    for (int im = 0; im < 2; ++im)
        ldsm4(base + (unsigned)((im * 16 * SA_ST + kb) * 2), a[im]);
}
__device__ __forceinline__ void ldsmB(unsigned base, int kb, unsigned b[2][4]) {
#pragma unroll
    for (int pr = 0; pr < 2; ++pr)
        ldsm4(base + (unsigned)((pr * 16 * SA_ST + kb) * 2), b[pr]);
}
__device__ __forceinline__ void ldsmBt(unsigned base, int kb, unsigned b[2][4]) {
#pragma unroll
    for (int pr = 0; pr < 2; ++pr)
        ldsm4t(base + (unsigned)((kb * SB_ST + pr * 16) * 2), b[pr]);
}
__device__ __forceinline__ void mma8(float acc[2][4][4], unsigned a[2][4], unsigned b[2][4]) {
#pragma unroll
    for (int im = 0; im < 2; ++im)
#pragma unroll
        for (int jn = 0; jn < 4; ++jn)
            mma_f16(acc[im][jn], a[im], &b[jn >> 1][(jn & 1) * 2]);
}

// BK=64 step, NT: 4 k16 sub-steps with fragment double-buffering.
__device__ __forceinline__ void mma_step_NT(unsigned aAddr, unsigned bAddr,
                                            float acc[2][4][4]) {
    unsigned a[2][2][4], b[2][2][4];
    ldsmA(aAddr, 0, a[0]); ldsmB(bAddr, 0, b[0]);
#pragma unroll
    for (int s = 0; s < 4; ++s) {
        if (s < 3) {
            ldsmA(aAddr, (s + 1) * 16, a[(s + 1) & 1]);
            ldsmB(bAddr, (s + 1) * 16, b[(s + 1) & 1]);
        }
        mma8(acc, a[s & 1], b[s & 1]);
    }
}

// BK=64 step, NN (V via ldmatrix.trans), fragment double-buffered.
__device__ __forceinline__ void mma_step_NN(unsigned aAddr, unsigned bAddr,
                                            float acc[2][4][4]) {
    unsigned a[2][2][4], b[2][2][4];
    ldsmA(aAddr, 0, a[0]); ldsmBt(bAddr, 0, b[0]);
#pragma unroll
    for (int s = 0; s < 4; ++s) {
        if (s < 3) {
            ldsmA(aAddr, (s + 1) * 16, a[(s + 1) & 1]);
            ldsmBt(bAddr, (s + 1) * 16, b[(s + 1) & 1]);
        }
        mma8(acc, a[s & 1], b[s & 1]);
    }
}

// Per-thread ldmatrix bases (halves).
__device__ __forceinline__ int ldsm_a_off(int m_off, int lane) {
    return (m_off + (lane & 15)) * SA_ST + (lane >> 4) * 8;
}
__device__ __forceinline__ int ldsm_b_off(int n_off, int lane) {
    return (n_off + ((lane & 16) >> 1) + (lane & 7)) * SA_ST + ((lane >> 3) & 1) * 8;
}
__device__ __forceinline__ int ldsm_bt_off(int n_off, int lane) {
    return (((lane >> 3) & 1) * 8 + (lane & 7)) * SB_ST + n_off + (lane >> 4) * 8;
}

// ---------------------------------------------------------------------------
// 0) Convert inputs to fp16
// ---------------------------------------------------------------------------
__global__ __launch_bounds__(256) void round_x_kernel(const float4* __restrict__ x) {
    const int n4 = BATCH * SEQ * DIM / 4;
    __half2* dst = (__half2*)d_xh;
    for (int i = blockIdx.x * 256 + threadIdx.x; i < n4; i += gridDim.x * 256) {
        float4 v = x[i];
        dst[2 * i]     = __floats2half2_rn(v.x, v.y);
        dst[2 * i + 1] = __floats2half2_rn(v.z, v.w);
    }
}

__global__ __launch_bounds__(256) void round_w_kernel(const float4* __restrict__ Wq,
                                                      const float4* __restrict__ Wk,
                                                      const float4* __restrict__ Wv) {
    const float4* src = (blockIdx.z == 0) ? Wq : (blockIdx.z == 1) ? Wk : Wv;
    __half2* dst = (__half2*)d_Wh[blockIdx.z];
    const int n4 = DIM * DIM / 4;
    for (int i = blockIdx.x * 256 + threadIdx.x; i < n4; i += gridDim.x * 256) {
        float4 v = src[i];
        dst[2 * i]     = __floats2half2_rn(v.x, v.y);
        dst[2 * i + 1] = __floats2half2_rn(v.z, v.w);
    }
}

// ---------------------------------------------------------------------------
// 1) QKV projection: xh @ Wh^T  (NT; fp16 outputs)
// ---------------------------------------------------------------------------
__global__ __launch_bounds__(512, 1) void qkv_kernel() {
    extern __shared__ __half smem[];
    __half* sA = smem;
    __half* sB = smem + NSTG * STG_A;

    __half* out = (blockIdx.z == 0) ? d_Qh : (blockIdx.z == 1) ? d_Kh : d_Vh;
    const __half* W = d_Wh[blockIdx.z];

    const int m0 = blockIdx.y * 128, n0 = blockIdx.x * 128;
    const int t = threadIdx.x;
    const int wid = t >> 5, lane = t & 31, g = lane >> 2, c = lane & 3;
    const int m_off = (wid >> 2) * 32, n_off = (wid & 3) * 32;

    const unsigned sa_u = (unsigned)__cvta_generic_to_shared(sA) + 2u * ldsm_a_off(m_off, lane);
    const unsigned sb_u = (unsigned)__cvta_generic_to_shared(sB) + 2u * ldsm_b_off(n_off, lane);

    const __half* gA = d_xh + (size_t)m0 * DIM;
    const __half* gB = W + (size_t)n0 * DIM;

    float acc[2][4][4] = {};
    const int nIter = DIM / BK;            // 16

#pragma unroll
    for (int s = 0; s < 3; ++s) {
        if (s < nIter) {
            load_km(sA + s * STG_A, gA + s * BK, DIM, t);
            load_km(sB + s * STG_A, gB + s * BK, DIM, t);
        }
        cp_commit();
    }

    for (int it = 0; it < nIter; ++it) {
        cp_wait2();
        __syncthreads();
        const int pf = it + 3;
        if (pf < nIter) {
            const int ps = (pf & 3) * STG_A;
            load_km(sA + ps, gA + pf * BK, DIM, t);
            load_km(sB + ps, gB + pf * BK, DIM, t);
        }
        cp_commit();
        const unsigned so = (unsigned)((it & 3) * STG_A * 2);
        mma_step_NT(sa_u + so, sb_u + so, acc);
    }

#pragma unroll
    for (int im = 0; im < 2; ++im) {
#pragma unroll
        for (int jn = 0; jn < 4; ++jn) {
            const int row = m0 + m_off + im * 16 + g;
            const int col = n0 + n_off + jn * 8 + 2 * c;
            *(__half2*)(out + (size_t)row * DIM + col) =
                __floats2half2_rn(acc[im][jn][0], acc[im][jn][1]);
            *(__half2*)(out + (size_t)(row + 8) * DIM + col) =
                __floats2half2_rn(acc[im][jn][2], acc[im][jn][3]);
        }
    }
}

// ---------------------------------------------------------------------------
// 2) Scores: S[b] = (Q K^T) / 32  (NT, lower-tri tiles only, fp32 out)
// ---------------------------------------------------------------------------
__global__ __launch_bounds__(512, 1) void scores_kernel() {
    if (blockIdx.x > blockIdx.y) return;

    extern __shared__ __half smem[];
    __half* sA = smem;
    __half* sB = smem + NSTG * STG_A;

    const int b = blockIdx.z;
    const int m0 = blockIdx.y * 128, n0 = blockIdx.x * 128;
    const int t = threadIdx.x;
    const int wid = t >> 5, lane = t & 31, g = lane >> 2, c = lane & 3;
    const int m_off = (wid >> 2) * 32, n_off = (wid & 3) * 32;

    const unsigned sa_u = (unsigned)__cvta_generic_to_shared(sA) + 2u * ldsm_a_off(m_off, lane);
    const unsigned sb_u = (unsigned)__cvta_generic_to_shared(sB) + 2u * ldsm_b_off(n_off, lane);

    const __half* gA = d_Qh + (size_t)b * SEQ * DIM + (size_t)m0 * DIM;
    const __half* gB = d_Kh + (size_t)b * SEQ * DIM + (size_t)n0 * DIM;
    float* C = d_S + (size_t)b * SEQ * SEQ;

    float acc[2][4][4] = {};
    const int nIter = DIM / BK;

#pragma unroll
    for (int s = 0; s < 3; ++s) {
        if (s < nIter) {
            load_km(sA + s * STG_A, gA + s * BK, DIM, t);
            load_km(sB + s * STG_A, gB + s * BK, DIM, t);
        }
        cp_commit();
    }

    for (int it = 0; it < nIter; ++it) {
        cp_wait2();
        __syncthreads();
        const int pf = it + 3;
        if (pf < nIter) {
            const int ps = (pf & 3) * STG_A;
            load_km(sA + ps, gA + pf * BK, DIM, t);
            load_km(sB + ps, gB + pf * BK, DIM, t);
        }
        cp_commit();
        const unsigned so = (unsigned)((it & 3) * STG_A * 2);
        mma_step_NT(sa_u + so, sb_u + so, acc);
    }

    const float scale = 0.03125f;   // 1/sqrt(1024), folded into S
#pragma unroll
    for (int im = 0; im < 2; ++im) {
#pragma unroll
        for (int jn = 0; jn < 4; ++jn) {
            const int row = m0 + m_off + im * 16 + g;
            const int col = n0 + n_off + jn * 8 + 2 * c;
            *(float2*)(C + (size_t)row * SEQ + col) =
                make_float2(acc[im][jn][0] * scale, acc[im][jn][1] * scale);
            *(float2*)(C + (size_t)(row + 8) * SEQ + col) =
                make_float2(acc[im][jn][2] * scale, acc[im][jn][3] * scale);
        }
    }
}

// ---------------------------------------------------------------------------
// 3) Causal softmax on pre-scaled S: fp16 unnormalized exp (d_P) + 1/rowsum.
//    float4 reads, half2 writes.
// ---------------------------------------------------------------------------
__global__ __launch_bounds__(256) void softmax_kernel() {
    const int i = blockIdx.x;
    const int b = blockIdx.y;
    const float* row = d_S + ((size_t)b * SEQ + i) * SEQ;
    __half* rowP = d_P + ((size_t)b * SEQ + i) * SEQ;
    const int len = i + 1;
    const int n4 = len >> 2;
    const int tileEnd = ((i >> 7) + 1) << 7;
    const int t = threadIdx.x;
    const int lane = t & 31, w = t >> 5;
    const float4* row4 = (const float4*)row;

    __shared__ float red[8];

    float m = -CUDART_INF_F;
    for (int j = t; j < n4; j += 256) {
        float4 v = row4[j];
        m = fmaxf(m, fmaxf(fmaxf(v.x, v.y), fmaxf(v.z, v.w)));
    }
    for (int j = (n4 << 2) + t; j < len; j += 256) m = fmaxf(m, row[j]);
#pragma unroll
    for (int o = 16; o > 0; o >>= 1) m = fmaxf(m, __shfl_xor_sync(0xffffffffu, m, o));
    if (lane == 0) red[w] = m;
    __syncthreads();
    m = red[lane & 7];
#pragma unroll
    for (int o = 4; o > 0; o >>= 1) m = fmaxf(m, __shfl_xor_sync(0xffffffffu, m, o));
    __syncthreads();

    float sum = 0.f;
    for (int j = t; j < n4; j += 256) {
        float4 v = row4[j];
        float e0 = __expf(v.x - m), e1 = __expf(v.y - m);
        float e2 = __expf(v.z - m), e3 = __expf(v.w - m);
        sum += (e0 + e1) + (e2 + e3);
        *(__half2*)(rowP + 4 * j)     = __floats2half2_rn(e0, e1);
        *(__half2*)(rowP + 4 * j + 2) = __floats2half2_rn(e2, e3);
    }
    for (int j = (n4 << 2) + t; j < len; j += 256) {
        float e = __expf(row[j] - m);
        rowP[j] = __float2half_rn(e);
        sum += e;
    }
#pragma unroll
    for (int o = 16; o > 0; o >>= 1) sum += __shfl_xor_sync(0xffffffffu, sum, o);
    if (lane == 0) red[w] = sum;
    __syncthreads();
    sum = red[lane & 7];
#pragma unroll
    for (int o = 4; o > 0; o >>= 1) sum += __shfl_xor_sync(0xffffffffu, sum, o);
    if (t == 0) d_inv[b * SEQ + i] = 1.f / sum;

    for (int j = len + t; j < tileEnd; j += 256) rowP[j] = __half(0.f);
}

// ---------------------------------------------------------------------------
// 4) O = P @ V  (NN, k truncated at diagonal; epilogue scales by 1/rowsum)
// ---------------------------------------------------------------------------
__global__ __launch_bounds__(512, 1) void pv_kernel(float* __restrict__ out) {
    extern __shared__ __half smem[];
    __half* sA = smem;
    __half* sB = smem + NSTG * STG_A;

    const int b = blockIdx.z;
    const int m0 = blockIdx.y * 128, n0 = blockIdx.x * 128;
    const int t = threadIdx.x;
    const int wid = t >> 5, lane = t & 31, g = lane >> 2, c = lane & 3;
    const int m_off = (wid >> 2) * 32, n_off = (wid & 3) * 32;

    const unsigned sa_u = (unsigned)__cvta_generic_to_shared(sA) + 2u * ldsm_a_off(m_off, lane);
    const unsigned sb_u = (unsigned)__cvta_generic_to_shared(sB) + 2u * ldsm_bt_off(n_off, lane);

    const __half* gA = d_P + (size_t)b * SEQ * SEQ + (size_t)m0 * SEQ;
    const __half* gB = d_Vh + (size_t)b * SEQ * DIM + n0;
    float* C = out + (size_t)b * SEQ * DIM;

    float acc[2][4][4] = {};
    const int nIter = (m0 + 128) / BK;     // >= 2

#pragma unroll
    for (int s = 0; s < 3; ++s) {
        if (s < nIter) {
            load_km(sA + s * STG_A, gA + s * BK, SEQ, t);
            load_nm(sB + s * STG_BV, gB + (size_t)s * BK * DIM, DIM, t);
        }
        cp_commit();
    }

    for (int it = 0; it < nIter; ++it) {
        cp_wait2();
        __syncthreads();
        const int pf = it + 3;
        if (pf < nIter) {
            load_km(sA + (pf & 3) * STG_A, gA + pf * BK, SEQ, t);
            load_nm(sB + (pf & 3) * STG_BV, gB + (size_t)pf * BK * DIM, DIM, t);
        }
        cp_commit();
        mma_step_NN(sa_u + (unsigned)((it & 3) * STG_A * 2),
                    sb_u + (unsigned)((it & 3) * STG_BV * 2), acc);
    }

    const float* inv = d_inv + b * SEQ;
#pragma unroll
    for (int im = 0; im < 2; ++im) {
        const int row = m0 + m_off + im * 16 + g;
        const float i0 = inv[row], i1 = inv[row + 8];
#pragma unroll
        for (int jn = 0; jn < 4; ++jn) {
            const int col = n0 + n_off + jn * 8 + 2 * c;
            *(float2*)(C + (size_t)row * DIM + col) =
                make_float2(acc[im][jn][0] * i0, acc[im][jn][1] * i0);
            *(float2*)(C + (size_t)(row + 8) * DIM + col) =
                make_float2(acc[im][jn][2] * i1, acc[im][jn][3] * i1);
        }
    }
}

extern "C" void kernel_launch(void* const* d_in, const int* in_sizes, int n_in,
                              void* d_out, int out_size) {
    const float* x  = (const float*)d_in[0];
    const float* Wq = (const float*)d_in[1];
    const float* Wk = (const float*)d_in[2];
    const float* Wv = (const float*)d_in[3];
    float* out = (float*)d_out;

    cudaFuncSetAttribute(qkv_kernel,    cudaFuncAttributeMaxDynamicSharedMemorySize, SMEM_NT);
    cudaFuncSetAttribute(scores_kernel, cudaFuncAttributeMaxDynamicSharedMemorySize, SMEM_NT);
    cudaFuncSetAttribute(pv_kernel,     cudaFuncAttributeMaxDynamicSharedMemorySize, SMEM_PV);

    round_x_kernel<<<512, 256>>>((const float4*)x);
    round_w_kernel<<<dim3(64, 1, 3), 256>>>((const float4*)Wq, (const float4*)Wk,
                                            (const float4*)Wv);

    qkv_kernel<<<dim3(DIM / 128, (BATCH * SEQ) / 128, 3), 512, SMEM_NT>>>();
    scores_kernel<<<dim3(SEQ / 128, SEQ / 128, BATCH), 512, SMEM_NT>>>();
    softmax_kernel<<<dim3(SEQ, BATCH), 256>>>();
    pv_kernel<<<dim3(DIM / 128, SEQ / 128, BATCH), 512, SMEM_PV>>>(out);
}

// round 16
// speedup vs baseline: 1.7324x; 1.7324x over previous
#include <cuda_runtime.h>
#include <cuda_fp16.h>
#include <math_constants.h>

#define BATCH 4
#define SEQ   2048
#define DIM   1024

// Scratch (static device arrays: allocation-guard-safe)
__device__ __half d_Qh[BATCH * SEQ * DIM];
__device__ __half d_Kh[BATCH * SEQ * DIM];
__device__ __half d_Vh[BATCH * SEQ * DIM];
__device__ float  d_S[(size_t)BATCH * SEQ * SEQ];   // fp32 scores (pre-scaled by 1/32)
__device__ __half d_P[(size_t)BATCH * SEQ * SEQ];   // unnormalized probs (fp16)
__device__ float  d_inv[BATCH * SEQ];               // 1/rowsum for deferred normalize
__device__ __half d_xh[BATCH * SEQ * DIM];          // fp16 x
__device__ __half d_Wh[3][DIM * DIM];               // fp16 Wq/Wk/Wv

// ---------------------------------------------------------------------------
// FP16 mma.sync (m16n8k16, f32 acc) GEMM: block tile 128x128, BK=32,
// 3-stage cp.async pipeline, ONE __syncthreads per iteration, ldmatrix.
// 512 threads = 16 warps (4x4), warp tile 32x32 -> 32 acc regs/thread.
// (Round-13 winning configuration.)
// ---------------------------------------------------------------------------

#define BK 32        // halves of K per stage (2 k16 steps)
#define SA_ST 40     // 32 + 8 pad (halves): rows at 80B -> banks 20r%32 distinct
#define SB_ST 136    // 128 + 8 pad (halves) for [k][n] V tile (272B rows)
#define NSTG 3
#define STG_A (128 * SA_ST)      // halves per A (or NT-B) stage
#define STG_B (BK * SB_ST)       // halves per NN-B stage

#define SMEM_NT (NSTG * STG_A * 2 * 2)                 // 61440 B
#define SMEM_PV (NSTG * STG_A * 2 + NSTG * STG_B * 2)  // 56832 B

__device__ __forceinline__ void mma_f16(float* d, const unsigned* a, const unsigned* b) {
    asm volatile(
        "mma.sync.aligned.m16n8k16.row.col.f32.f16.f16.f32 "
        "{%0,%1,%2,%3}, {%4,%5,%6,%7}, {%8,%9}, {%0,%1,%2,%3};\n"
        : "+f"(d[0]), "+f"(d[1]), "+f"(d[2]), "+f"(d[3])
        : "r"(a[0]), "r"(a[1]), "r"(a[2]), "r"(a[3]), "r"(b[0]), "r"(b[1]));
}

__device__ __forceinline__ void ldsm4(unsigned addr, unsigned r[4]) {
    asm volatile("ldmatrix.sync.aligned.m8n8.x4.shared.b16 {%0,%1,%2,%3}, [%4];"
                 : "=r"(r[0]), "=r"(r[1]), "=r"(r[2]), "=r"(r[3]) : "r"(addr));
}
__device__ __forceinline__ void ldsm4t(unsigned addr, unsigned r[4]) {
    asm volatile("ldmatrix.sync.aligned.m8n8.x4.trans.shared.b16 {%0,%1,%2,%3}, [%4];"
                 : "=r"(r[0]), "=r"(r[1]), "=r"(r[2]), "=r"(r[3]) : "r"(addr));
}

__device__ __forceinline__ void cp16(void* smem, const void* gmem) {
    unsigned s = (unsigned)__cvta_generic_to_shared(smem);
    asm volatile("cp.async.cg.shared.global [%0], [%1], 16;\n" :: "r"(s), "l"(gmem));
}
__device__ __forceinline__ void cp_commit() { asm volatile("cp.async.commit_group;\n"); }
__device__ __forceinline__ void cp_wait1()  { asm volatile("cp.async.wait_group 1;\n"); }

// 128x32h K-contiguous tile into smem [128][SA_ST] (1 cp16/thread @512 thr).
__device__ __forceinline__ void load_km(__half* s, const __half* g, int ld, int t) {
    const int row = t >> 2;            // 0..127
    const int c8  = (t & 3) << 3;      // 0,8,16,24
    cp16(&s[row * SA_ST + c8], g + (size_t)row * ld + c8);
}

// 32x128h [k][n] tile (V) into smem [32][SB_ST] (1 cp16/thread @512 thr).
__device__ __forceinline__ void load_nm(__half* s, const __half* g, int ld, int t) {
    const int kr = t >> 4;             // 0..31
    const int c8 = (t & 15) << 3;      // 0..120
    cp16(&s[kr * SB_ST + c8], g + (size_t)kr * ld + c8);
}

// BK=32 (2x k16) compute step, NT, ldmatrix both operands.
__device__ __forceinline__ void mma_step_NT(unsigned aAddr, unsigned bAddr,
                                            float acc[2][4][4]) {
#pragma unroll
    for (int kb = 0; kb < BK; kb += 16) {
        unsigned a[2][4], b2[2][4];
#pragma unroll
        for (int im = 0; im < 2; ++im)
            ldsm4(aAddr + (unsigned)((im * 16 * SA_ST + kb) * 2), a[im]);
#pragma unroll
        for (int pr = 0; pr < 2; ++pr)
            ldsm4(bAddr + (unsigned)((pr * 16 * SA_ST + kb) * 2), b2[pr]);
#pragma unroll
        for (int im = 0; im < 2; ++im)
#pragma unroll
            for (int jn = 0; jn < 4; ++jn)
                mma_f16(acc[im][jn], a[im], &b2[jn >> 1][(jn & 1) * 2]);
    }
}

// BK=32 compute step, NN: A via ldmatrix, B (V, [k][n]) via ldmatrix.trans.
__device__ __forceinline__ void mma_step_NN(unsigned aAddr, unsigned bAddr,
                                            float acc[2][4][4]) {
#pragma unroll
    for (int kb = 0; kb < BK; kb += 16) {
        unsigned a[2][4], b2[2][4];
#pragma unroll
        for (int im = 0; im < 2; ++im)
            ldsm4(aAddr + (unsigned)((im * 16 * SA_ST + kb) * 2), a[im]);
#pragma unroll
        for (int pr = 0; pr < 2; ++pr)
            ldsm4t(bAddr + (unsigned)((kb * SB_ST + pr * 16) * 2), b2[pr]);
#pragma unroll
        for (int im = 0; im < 2; ++im)
#pragma unroll
            for (int jn = 0; jn < 4; ++jn)
                mma_f16(acc[im][jn], a[im], &b2[jn >> 1][(jn & 1) * 2]);
    }
}

// Per-thread ldmatrix A row base (halves): lanes 0-15 rows, 16-31 at +8 k.
__device__ __forceinline__ int ldsm_a_off(int m_off, int lane) {
    return (m_off + (lane & 15)) * SA_ST + (lane >> 4) * 8;
}
// Per-thread ldmatrix B (NT) base: r0/r1 = n0-7 k0/k8, r2/r3 = n8-15 k0/k8.
__device__ __forceinline__ int ldsm_b_off(int n_off, int lane) {
    return (n_off + ((lane & 16) >> 1) + (lane & 7)) * SA_ST + ((lane >> 3) & 1) * 8;
}
// Per-thread ldmatrix.trans B (NN, V): lanes give k-rows, n col 16B groups.
__device__ __forceinline__ int ldsm_bt_off(int n_off, int lane) {
    return (((lane >> 3) & 1) * 8 + (lane & 7)) * SB_ST + n_off + (lane >> 4) * 8;
}

// ---------------------------------------------------------------------------
// 0) Convert inputs to fp16
// ---------------------------------------------------------------------------
__global__ __launch_bounds__(256) void round_x_kernel(const float4* __restrict__ x) {
    const int n4 = BATCH * SEQ * DIM / 4;
    __half2* dst = (__half2*)d_xh;
    for (int i = blockIdx.x * 256 + threadIdx.x; i < n4; i += gridDim.x * 256) {
        float4 v = x[i];
        dst[2 * i]     = __floats2half2_rn(v.x, v.y);
        dst[2 * i + 1] = __floats2half2_rn(v.z, v.w);
    }
}

__global__ __launch_bounds__(256) void round_w_kernel(const float4* __restrict__ Wq,
                                                      const float4* __restrict__ Wk,
                                                      const float4* __restrict__ Wv) {
    const float4* src = (blockIdx.z == 0) ? Wq : (blockIdx.z == 1) ? Wk : Wv;
    __half2* dst = (__half2*)d_Wh[blockIdx.z];
    const int n4 = DIM * DIM / 4;
    for (int i = blockIdx.x * 256 + threadIdx.x; i < n4; i += gridDim.x * 256) {
        float4 v = src[i];
        dst[2 * i]     = __floats2half2_rn(v.x, v.y);
        dst[2 * i + 1] = __floats2half2_rn(v.z, v.w);
    }
}

// ---------------------------------------------------------------------------
// 1) QKV projection: xh @ Wh^T  (NT; fp16 outputs)
// ---------------------------------------------------------------------------
__global__ __launch_bounds__(512, 2) void qkv_kernel() {
    extern __shared__ __half smem[];
    __half* sA = smem;
    __half* sB = smem + NSTG * STG_A;

    __half* out = (blockIdx.z == 0) ? d_Qh : (blockIdx.z == 1) ? d_Kh : d_Vh;
    const __half* W = d_Wh[blockIdx.z];

    const int m0 = blockIdx.y * 128, n0 = blockIdx.x * 128;
    const int t = threadIdx.x;
    const int wid = t >> 5, lane = t & 31, g = lane >> 2, c = lane & 3;
    const int m_off = (wid >> 2) * 32, n_off = (wid & 3) * 32;

    const unsigned sa_u = (unsigned)__cvta_generic_to_shared(sA) + 2u * ldsm_a_off(m_off, lane);
    const unsigned sb_u = (unsigned)__cvta_generic_to_shared(sB) + 2u * ldsm_b_off(n_off, lane);

    const __half* gA = d_xh + (size_t)m0 * DIM;
    const __half* gB = W + (size_t)n0 * DIM;

    float acc[2][4][4] = {};
    const int nIter = DIM / BK;            // 32

    load_km(sA, gA, DIM, t); load_km(sB, gB, DIM, t); cp_commit();
    load_km(sA + STG_A, gA + BK, DIM, t);
    load_km(sB + STG_A, gB + BK, DIM, t); cp_commit();

    for (int it = 0; it < nIter; ++it) {
        cp_wait1();
        __syncthreads();
        const int pf = it + 2;
        if (pf < nIter) {
            const int ps = (pf % 3) * STG_A;
            load_km(sA + ps, gA + pf * BK, DIM, t);
            load_km(sB + ps, gB + pf * BK, DIM, t);
        }
        cp_commit();
        const unsigned so = (unsigned)((it % 3) * STG_A * 2);
        mma_step_NT(sa_u + so, sb_u + so, acc);
    }

#pragma unroll
    for (int im = 0; im < 2; ++im) {
#pragma unroll
        for (int jn = 0; jn < 4; ++jn) {
            const int row = m0 + m_off + im * 16 + g;
            const int col = n0 + n_off + jn * 8 + 2 * c;
            *(__half2*)(out + (size_t)row * DIM + col) =
                __floats2half2_rn(acc[im][jn][0], acc[im][jn][1]);
            *(__half2*)(out + (size_t)(row + 8) * DIM + col) =
                __floats2half2_rn(acc[im][jn][2], acc[im][jn][3]);
        }
    }
}

// ---------------------------------------------------------------------------
// 2) Scores: S[b] = (Q K^T) / 32  (NT, lower-tri tiles only, fp32 out,
//    scale folded into the register epilogue)
// ---------------------------------------------------------------------------
__global__ __launch_bounds__(512, 2) void scores_kernel() {
    if (blockIdx.x > blockIdx.y) return;

    extern __shared__ __half smem[];
    __half* sA = smem;
    __half* sB = smem + NSTG * STG_A;

    const int b = blockIdx.z;
    const int m0 = blockIdx.y * 128, n0 = blockIdx.x * 128;
    const int t = threadIdx.x;
    const int wid = t >> 5, lane = t & 31, g = lane >> 2, c = lane & 3;
    const int m_off = (wid >> 2) * 32, n_off = (wid & 3) * 32;

    const unsigned sa_u = (unsigned)__cvta_generic_to_shared(sA) + 2u * ldsm_a_off(m_off, lane);
    const unsigned sb_u = (unsigned)__cvta_generic_to_shared(sB) + 2u * ldsm_b_off(n_off, lane);

    const __half* gA = d_Qh + (size_t)b * SEQ * DIM + (size_t)m0 * DIM;
    const __half* gB = d_Kh + (size_t)b * SEQ * DIM + (size_t)n0 * DIM;
    float* C = d_S + (size_t)b * SEQ * SEQ;

    float acc[2][4][4] = {};
    const int nIter = DIM / BK;

    load_km(sA, gA, DIM, t); load_km(sB, gB, DIM, t); cp_commit();
    load_km(sA + STG_A, gA + BK, DIM, t);
    load_km(sB + STG_A, gB + BK, DIM, t); cp_commit();

    for (int it = 0; it < nIter; ++it) {
        cp_wait1();
        __syncthreads();
        const int pf = it + 2;
        if (pf < nIter) {
            const int ps = (pf % 3) * STG_A;
            load_km(sA + ps, gA + pf * BK, DIM, t);
            load_km(sB + ps, gB + pf * BK, DIM, t);
        }
        cp_commit();
        const unsigned so = (unsigned)((it % 3) * STG_A * 2);
        mma_step_NT(sa_u + so, sb_u + so, acc);
    }

    const float scale = 0.03125f;   // 1/sqrt(1024), folded into S
#pragma unroll
    for (int im = 0; im < 2; ++im) {
#pragma unroll
        for (int jn = 0; jn < 4; ++jn) {
            const int row = m0 + m_off + im * 16 + g;
            const int col = n0 + n_off + jn * 8 + 2 * c;
            *(float2*)(C + (size_t)row * SEQ + col) =
                make_float2(acc[im][jn][0] * scale, acc[im][jn][1] * scale);
            *(float2*)(C + (size_t)(row + 8) * SEQ + col) =
                make_float2(acc[im][jn][2] * scale, acc[im][jn][3] * scale);
        }
    }
}

// ---------------------------------------------------------------------------
// 3) Causal softmax on pre-scaled S: fp16 unnormalized exp (d_P) + 1/rowsum.
//    float4 reads, half2 writes.
// ---------------------------------------------------------------------------
__global__ __launch_bounds__(256) void softmax_kernel() {
    const int i = blockIdx.x;
    const int b = blockIdx.y;
    const float* row = d_S + ((size_t)b * SEQ + i) * SEQ;
    __half* rowP = d_P + ((size_t)b * SEQ + i) * SEQ;
    const int len = i + 1;
    const int n4 = len >> 2;
    const int tileEnd = ((i >> 7) + 1) << 7;
    const int t = threadIdx.x;
    const int lane = t & 31, w = t >> 5;
    const float4* row4 = (const float4*)row;

    __shared__ float red[8];

    float m = -CUDART_INF_F;
    for (int j = t; j < n4; j += 256) {
        float4 v = row4[j];
        m = fmaxf(m, fmaxf(fmaxf(v.x, v.y), fmaxf(v.z, v.w)));
    }
    for (int j = (n4 << 2) + t; j < len; j += 256) m = fmaxf(m, row[j]);
#pragma unroll
    for (int o = 16; o > 0; o >>= 1) m = fmaxf(m, __shfl_xor_sync(0xffffffffu, m, o));
    if (lane == 0) red[w] = m;
    __syncthreads();
    m = red[lane & 7];
#pragma unroll
    for (int o = 4; o > 0; o >>= 1) m = fmaxf(m, __shfl_xor_sync(0xffffffffu, m, o));
    __syncthreads();

    float sum = 0.f;
    for (int j = t; j < n4; j += 256) {
        float4 v = row4[j];
        float e0 = __expf(v.x - m), e1 = __expf(v.y - m);
        float e2 = __expf(v.z - m), e3 = __expf(v.w - m);
        sum += (e0 + e1) + (e2 + e3);
        *(__half2*)(rowP + 4 * j)     = __floats2half2_rn(e0, e1);
        *(__half2*)(rowP + 4 * j + 2) = __floats2half2_rn(e2, e3);
    }
    for (int j = (n4 << 2) + t; j < len; j += 256) {
        float e = __expf(row[j] - m);
        rowP[j] = __float2half_rn(e);
        sum += e;
    }
#pragma unroll
    for (int o = 16; o > 0; o >>= 1) sum += __shfl_xor_sync(0xffffffffu, sum, o);
    if (lane == 0) red[w] = sum;
    __syncthreads();
    sum = red[lane & 7];
#pragma unroll
    for (int o = 4; o > 0; o >>= 1) sum += __shfl_xor_sync(0xffffffffu, sum, o);
    if (t == 0) d_inv[b * SEQ + i] = 1.f / sum;

    for (int j = len + t; j < tileEnd; j += 256) rowP[j] = __half(0.f);
}

// ---------------------------------------------------------------------------
// 4) O = P @ V  (NN, k truncated at diagonal; epilogue scales by 1/rowsum)
// ---------------------------------------------------------------------------
__global__ __launch_bounds__(512, 2) void pv_kernel(float* __restrict__ out) {
    extern __shared__ __half smem[];
    __half* sA = smem;
    __half* sB = smem + NSTG * STG_A;

    const int b = blockIdx.z;
    const int m0 = blockIdx.y * 128, n0 = blockIdx.x * 128;
    const int t = threadIdx.x;
    const int wid = t >> 5, lane = t & 31, g = lane >> 2, c = lane & 3;
    const int m_off = (wid >> 2) * 32, n_off = (wid & 3) * 32;

    const unsigned sa_u = (unsigned)__cvta_generic_to_shared(sA) + 2u * ldsm_a_off(m_off, lane);
    const unsigned sb_u = (unsigned)__cvta_generic_to_shared(sB) + 2u * ldsm_bt_off(n_off, lane);

    const __half* gA = d_P + (size_t)b * SEQ * SEQ + (size_t)m0 * SEQ;
    const __half* gB = d_Vh + (size_t)b * SEQ * DIM + n0;
    float* C = out + (size_t)b * SEQ * DIM;

    float acc[2][4][4] = {};
    const int nIter = (m0 + 128) / BK;     // >= 4

    load_km(sA, gA, SEQ, t); load_nm(sB, gB, DIM, t); cp_commit();
    load_km(sA + STG_A, gA + BK, SEQ, t);
    load_nm(sB + STG_B, gB + (size_t)BK * DIM, DIM, t); cp_commit();

    for (int it = 0; it < nIter; ++it) {
        cp_wait1();
        __syncthreads();
        const int pf = it + 2;
        if (pf < nIter) {
            load_km(sA + (pf % 3) * STG_A, gA + pf * BK, SEQ, t);
            load_nm(sB + (pf % 3) * STG_B, gB + (size_t)pf * BK * DIM, DIM, t);
        }
        cp_commit();
        mma_step_NN(sa_u + (unsigned)((it % 3) * STG_A * 2),
                    sb_u + (unsigned)((it % 3) * STG_B * 2), acc);
    }

    const float* inv = d_inv + b * SEQ;
#pragma unroll
    for (int im = 0; im < 2; ++im) {
        const int row = m0 + m_off + im * 16 + g;
        const float i0 = inv[row], i1 = inv[row + 8];
#pragma unroll
        for (int jn = 0; jn < 4; ++jn) {
            const int col = n0 + n_off + jn * 8 + 2 * c;
            *(float2*)(C + (size_t)row * DIM + col) =
                make_float2(acc[im][jn][0] * i0, acc[im][jn][1] * i0);
            *(float2*)(C + (size_t)(row + 8) * DIM + col) =
                make_float2(acc[im][jn][2] * i1, acc[im][jn][3] * i1);
        }
    }
}

extern "C" void kernel_launch(void* const* d_in, const int* in_sizes, int n_in,
                              void* d_out, int out_size) {
    const float* x  = (const float*)d_in[0];
    const float* Wq = (const float*)d_in[1];
    const float* Wk = (const float*)d_in[2];
    const float* Wv = (const float*)d_in[3];
    float* out = (float*)d_out;

    cudaFuncSetAttribute(qkv_kernel,    cudaFuncAttributeMaxDynamicSharedMemorySize, SMEM_NT);
    cudaFuncSetAttribute(scores_kernel, cudaFuncAttributeMaxDynamicSharedMemorySize, SMEM_NT);
    cudaFuncSetAttribute(pv_kernel,     cudaFuncAttributeMaxDynamicSharedMemorySize, SMEM_PV);

    round_x_kernel<<<512, 256>>>((const float4*)x);
    round_w_kernel<<<dim3(64, 1, 3), 256>>>((const float4*)Wq, (const float4*)Wk,
                                            (const float4*)Wv);

    qkv_kernel<<<dim3(DIM / 128, (BATCH * SEQ) / 128, 3), 512, SMEM_NT>>>();
    scores_kernel<<<dim3(SEQ / 128, SEQ / 128, BATCH), 512, SMEM_NT>>>();
    softmax_kernel<<<dim3(SEQ, BATCH), 256>>>();
    pv_kernel<<<dim3(DIM / 128, SEQ / 128, BATCH), 512, SMEM_PV>>>(out);
}

// round 17
// speedup vs baseline: 1.8350x; 1.0592x over previous
#include <cuda_runtime.h>
#include <cuda_fp16.h>
#include <math_constants.h>

#define BATCH 4
#define SEQ   2048
#define DIM   1024

// Scratch (static device arrays: allocation-guard-safe)
__device__ __half d_Qh[BATCH * SEQ * DIM];
__device__ __half d_Kh[BATCH * SEQ * DIM];
__device__ __half d_Vh[BATCH * SEQ * DIM];
__device__ float  d_S[(size_t)BATCH * SEQ * SEQ];   // fp32 scores (pre-scaled by 1/32)
__device__ __half d_P[(size_t)BATCH * SEQ * SEQ];   // unnormalized probs (fp16)
__device__ float  d_inv[BATCH * SEQ];               // 1/rowsum for deferred normalize
__device__ __half d_xh[BATCH * SEQ * DIM];          // fp16 x
__device__ __half d_Wh[3][DIM * DIM];               // fp16 Wq/Wk/Wv

// ---------------------------------------------------------------------------
// FP16 mma.sync (m16n8k16, f32 acc) GEMM: block tile 128x128, BK=64
// (4 k16 sub-steps per stage -> half the barriers of BK=32), 3-stage
// cp.async ring, ONE __syncthreads per iteration, ldmatrix fragments.
// 512 threads = 16 warps (4x4), warp tile 32x32, 2 CTAs/SM.
// ---------------------------------------------------------------------------

#define BK 64        // halves of K per stage (4 k16 sub-steps)
#define SA_ST 72     // 64 + 8 pad (halves): ldsm rows at bank step 4 -> distinct
#define SB_ST 136    // 128 + 8 pad (halves) for [k][n] V tile
#define NSTG 3
#define STG_A (128 * SA_ST)      // halves per A (or NT-B) stage (9216)
#define STG_B (BK * SB_ST)       // halves per V stage           (8704)

#define SMEM_NT (NSTG * STG_A * 2 * 2)                 // 110592 B/CTA
#define SMEM_PV (NSTG * STG_A * 2 + NSTG * STG_B * 2)  // 107520 B/CTA

__device__ __forceinline__ void mma_f16(float* d, const unsigned* a, const unsigned* b) {
    asm volatile(
        "mma.sync.aligned.m16n8k16.row.col.f32.f16.f16.f32 "
        "{%0,%1,%2,%3}, {%4,%5,%6,%7}, {%8,%9}, {%0,%1,%2,%3};\n"
        : "+f"(d[0]), "+f"(d[1]), "+f"(d[2]), "+f"(d[3])
        : "r"(a[0]), "r"(a[1]), "r"(a[2]), "r"(a[3]), "r"(b[0]), "r"(b[1]));
}

__device__ __forceinline__ void ldsm4(unsigned addr, unsigned r[4]) {
    asm volatile("ldmatrix.sync.aligned.m8n8.x4.shared.b16 {%0,%1,%2,%3}, [%4];"
                 : "=r"(r[0]), "=r"(r[1]), "=r"(r[2]), "=r"(r[3]) : "r"(addr));
}
__device__ __forceinline__ void ldsm4t(unsigned addr, unsigned r[4]) {
    asm volatile("ldmatrix.sync.aligned.m8n8.x4.trans.shared.b16 {%0,%1,%2,%3}, [%4];"
                 : "=r"(r[0]), "=r"(r[1]), "=r"(r[2]), "=r"(r[3]) : "r"(addr));
}

__device__ __forceinline__ void cp16(void* smem, const void* gmem) {
    unsigned s = (unsigned)__cvta_generic_to_shared(smem);
    asm volatile("cp.async.cg.shared.global [%0], [%1], 16;\n" :: "r"(s), "l"(gmem));
}
__device__ __forceinline__ void cp_commit() { asm volatile("cp.async.commit_group;\n"); }
__device__ __forceinline__ void cp_wait1()  { asm volatile("cp.async.wait_group 1;\n"); }

// 128x64h K-contiguous tile into smem [128][SA_ST] (2 cp16/thread @512 thr).
__device__ __forceinline__ void load_km(__half* s, const __half* g, int ld, int t) {
#pragma unroll
    for (int i = 0; i < 2; ++i) {
        const int cid = t + i * 512;       // 0..1023
        const int row = cid >> 3, ch = cid & 7;
        cp16(&s[row * SA_ST + ch * 8], g + (size_t)row * ld + ch * 8);
    }
}

// 64x128h [k][n] V tile into smem [64][SB_ST] (2 cp16/thread @512 thr).
__device__ __forceinline__ void load_nm(__half* s, const __half* g, int ld, int t) {
#pragma unroll
    for (int i = 0; i < 2; ++i) {
        const int cid = t + i * 512;
        const int row = cid >> 4, ch = cid & 15;
        cp16(&s[row * SB_ST + ch * 8], g + (size_t)row * ld + ch * 8);
    }
}

// BK=64 compute step, NT: 4 k16 sub-steps, fragment regs reused (no growth).
__device__ __forceinline__ void mma_step_NT(unsigned aAddr, unsigned bAddr,
                                            float acc[2][4][4]) {
#pragma unroll
    for (int kb = 0; kb < BK; kb += 16) {
        unsigned a[2][4], b2[2][4];
#pragma unroll
        for (int im = 0; im < 2; ++im)
            ldsm4(aAddr + (unsigned)((im * 16 * SA_ST + kb) * 2), a[im]);
#pragma unroll
        for (int pr = 0; pr < 2; ++pr)
            ldsm4(bAddr + (unsigned)((pr * 16 * SA_ST + kb) * 2), b2[pr]);
#pragma unroll
        for (int im = 0; im < 2; ++im)
#pragma unroll
            for (int jn = 0; jn < 4; ++jn)
                mma_f16(acc[im][jn], a[im], &b2[jn >> 1][(jn & 1) * 2]);
    }
}

// BK=64 compute step, NN: A via ldmatrix, B (V, [k][n]) via ldmatrix.trans.
__device__ __forceinline__ void mma_step_NN(unsigned aAddr, unsigned bAddr,
                                            float acc[2][4][4]) {
#pragma unroll
    for (int kb = 0; kb < BK; kb += 16) {
        unsigned a[2][4], b2[2][4];
#pragma unroll
        for (int im = 0; im < 2; ++im)
            ldsm4(aAddr + (unsigned)((im * 16 * SA_ST + kb) * 2), a[im]);
#pragma unroll
        for (int pr = 0; pr < 2; ++pr)
            ldsm4t(bAddr + (unsigned)((kb * SB_ST + pr * 16) * 2), b2[pr]);
#pragma unroll
        for (int im = 0; im < 2; ++im)
#pragma unroll
            for (int jn = 0; jn < 4; ++jn)
                mma_f16(acc[im][jn], a[im], &b2[jn >> 1][(jn & 1) * 2]);
    }
}

// Per-thread ldmatrix A row base (halves): lanes 0-15 rows, 16-31 at +8 k.
__device__ __forceinline__ int ldsm_a_off(int m_off, int lane) {
    return (m_off + (lane & 15)) * SA_ST + (lane >> 4) * 8;
}
// Per-thread ldmatrix B (NT) base: r0/r1 = n0-7 k0/k8, r2/r3 = n8-15 k0/k8.
__device__ __forceinline__ int ldsm_b_off(int n_off, int lane) {
    return (n_off + ((lane & 16) >> 1) + (lane & 7)) * SA_ST + ((lane >> 3) & 1) * 8;
}
// Per-thread ldmatrix.trans B (NN, V): lanes give k-rows, n col 16B groups.
__device__ __forceinline__ int ldsm_bt_off(int n_off, int lane) {
    return (((lane >> 3) & 1) * 8 + (lane & 7)) * SB_ST + n_off + (lane >> 4) * 8;
}

// ---------------------------------------------------------------------------
// 0) Convert inputs to fp16
// ---------------------------------------------------------------------------
__global__ __launch_bounds__(256) void round_x_kernel(const float4* __restrict__ x) {
    const int n4 = BATCH * SEQ * DIM / 4;
    __half2* dst = (__half2*)d_xh;
    for (int i = blockIdx.x * 256 + threadIdx.x; i < n4; i += gridDim.x * 256) {
        float4 v = x[i];
        dst[2 * i]     = __floats2half2_rn(v.x, v.y);
        dst[2 * i + 1] = __floats2half2_rn(v.z, v.w);
    }
}

__global__ __launch_bounds__(256) void round_w_kernel(const float4* __restrict__ Wq,
                                                      const float4* __restrict__ Wk,
                                                      const float4* __restrict__ Wv) {
    const float4* src = (blockIdx.z == 0) ? Wq : (blockIdx.z == 1) ? Wk : Wv;
    __half2* dst = (__half2*)d_Wh[blockIdx.z];
    const int n4 = DIM * DIM / 4;
    for (int i = blockIdx.x * 256 + threadIdx.x; i < n4; i += gridDim.x * 256) {
        float4 v = src[i];
        dst[2 * i]     = __floats2half2_rn(v.x, v.y);
        dst[2 * i + 1] = __floats2half2_rn(v.z, v.w);
    }
}

// ---------------------------------------------------------------------------
// 1) QKV projection: xh @ Wh^T  (NT; fp16 outputs)
// ---------------------------------------------------------------------------
__global__ __launch_bounds__(512, 2) void qkv_kernel() {
    extern __shared__ __half smem[];
    __half* sA = smem;
    __half* sB = smem + NSTG * STG_A;

    __half* out = (blockIdx.z == 0) ? d_Qh : (blockIdx.z == 1) ? d_Kh : d_Vh;
    const __half* W = d_Wh[blockIdx.z];

    const int m0 = blockIdx.y * 128, n0 = blockIdx.x * 128;
    const int t = threadIdx.x;
    const int wid = t >> 5, lane = t & 31, g = lane >> 2, c = lane & 3;
    const int m_off = (wid >> 2) * 32, n_off = (wid & 3) * 32;

    const unsigned sa_u = (unsigned)__cvta_generic_to_shared(sA) + 2u * ldsm_a_off(m_off, lane);
    const unsigned sb_u = (unsigned)__cvta_generic_to_shared(sB) + 2u * ldsm_b_off(n_off, lane);

    const __half* gA = d_xh + (size_t)m0 * DIM;
    const __half* gB = W + (size_t)n0 * DIM;

    float acc[2][4][4] = {};
    const int nIter = DIM / BK;            // 16

    load_km(sA, gA, DIM, t); load_km(sB, gB, DIM, t); cp_commit();
    load_km(sA + STG_A, gA + BK, DIM, t);
    load_km(sB + STG_A, gB + BK, DIM, t); cp_commit();

    for (int it = 0; it < nIter; ++it) {
        cp_wait1();
        __syncthreads();
        const int pf = it + 2;
        if (pf < nIter) {
            const int ps = (pf % 3) * STG_A;
            load_km(sA + ps, gA + pf * BK, DIM, t);
            load_km(sB + ps, gB + pf * BK, DIM, t);
        }
        cp_commit();
        const unsigned so = (unsigned)((it % 3) * STG_A * 2);
        mma_step_NT(sa_u + so, sb_u + so, acc);
    }

#pragma unroll
    for (int im = 0; im < 2; ++im) {
#pragma unroll
        for (int jn = 0; jn < 4; ++jn) {
            const int row = m0 + m_off + im * 16 + g;
            const int col = n0 + n_off + jn * 8 + 2 * c;
            *(__half2*)(out + (size_t)row * DIM + col) =
                __floats2half2_rn(acc[im][jn][0], acc[im][jn][1]);
            *(__half2*)(out + (size_t)(row + 8) * DIM + col) =
                __floats2half2_rn(acc[im][jn][2], acc[im][jn][3]);
        }
    }
}

// ---------------------------------------------------------------------------
// 2) Scores: S[b] = (Q K^T) / 32  (NT, lower-tri tiles only, fp32 out,
//    scale folded into the register epilogue)
// ---------------------------------------------------------------------------
__global__ __launch_bounds__(512, 2) void scores_kernel() {
    if (blockIdx.x > blockIdx.y) return;

    extern __shared__ __half smem[];
    __half* sA = smem;
    __half* sB = smem + NSTG * STG_A;

    const int b = blockIdx.z;
    const int m0 = blockIdx.y * 128, n0 = blockIdx.x * 128;
    const int t = threadIdx.x;
    const int wid = t >> 5, lane = t & 31, g = lane >> 2, c = lane & 3;
    const int m_off = (wid >> 2) * 32, n_off = (wid & 3) * 32;

    const unsigned sa_u = (unsigned)__cvta_generic_to_shared(sA) + 2u * ldsm_a_off(m_off, lane);
    const unsigned sb_u = (unsigned)__cvta_generic_to_shared(sB) + 2u * ldsm_b_off(n_off, lane);

    const __half* gA = d_Qh + (size_t)b * SEQ * DIM + (size_t)m0 * DIM;
    const __half* gB = d_Kh + (size_t)b * SEQ * DIM + (size_t)n0 * DIM;
    float* C = d_S + (size_t)b * SEQ * SEQ;

    float acc[2][4][4] = {};
    const int nIter = DIM / BK;

    load_km(sA, gA, DIM, t); load_km(sB, gB, DIM, t); cp_commit();
    load_km(sA + STG_A, gA + BK, DIM, t);
    load_km(sB + STG_A, gB + BK, DIM, t); cp_commit();

    for (int it = 0; it < nIter; ++it) {
        cp_wait1();
        __syncthreads();
        const int pf = it + 2;
        if (pf < nIter) {
            const int ps = (pf % 3) * STG_A;
            load_km(sA + ps, gA + pf * BK, DIM, t);
            load_km(sB + ps, gB + pf * BK, DIM, t);
        }
        cp_commit();
        const unsigned so = (unsigned)((it % 3) * STG_A * 2);
        mma_step_NT(sa_u + so, sb_u + so, acc);
    }

    const float scale = 0.03125f;   // 1/sqrt(1024), folded into S
#pragma unroll
    for (int im = 0; im < 2; ++im) {
#pragma unroll
        for (int jn = 0; jn < 4; ++jn) {
            const int row = m0 + m_off + im * 16 + g;
            const int col = n0 + n_off + jn * 8 + 2 * c;
            *(float2*)(C + (size_t)row * SEQ + col) =
                make_float2(acc[im][jn][0] * scale, acc[im][jn][1] * scale);
            *(float2*)(C + (size_t)(row + 8) * SEQ + col) =
                make_float2(acc[im][jn][2] * scale, acc[im][jn][3] * scale);
        }
    }
}

// ---------------------------------------------------------------------------
// 3) Causal softmax on pre-scaled S: fp16 unnormalized exp (d_P) + 1/rowsum.
//    float4 reads, half2 writes.
// ---------------------------------------------------------------------------
__global__ __launch_bounds__(256) void softmax_kernel() {
    const int i = blockIdx.x;
    const int b = blockIdx.y;
    const float* row = d_S + ((size_t)b * SEQ + i) * SEQ;
    __half* rowP = d_P + ((size_t)b * SEQ + i) * SEQ;
    const int len = i + 1;
    const int n4 = len >> 2;
    const int tileEnd = ((i >> 7) + 1) << 7;
    const int t = threadIdx.x;
    const int lane = t & 31, w = t >> 5;
    const float4* row4 = (const float4*)row;

    __shared__ float red[8];

    float m = -CUDART_INF_F;
    for (int j = t; j < n4; j += 256) {
        float4 v = row4[j];
        m = fmaxf(m, fmaxf(fmaxf(v.x, v.y), fmaxf(v.z, v.w)));
    }
    for (int j = (n4 << 2) + t; j < len; j += 256) m = fmaxf(m, row[j]);
#pragma unroll
    for (int o = 16; o > 0; o >>= 1) m = fmaxf(m, __shfl_xor_sync(0xffffffffu, m, o));
    if (lane == 0) red[w] = m;
    __syncthreads();
    m = red[lane & 7];
#pragma unroll
    for (int o = 4; o > 0; o >>= 1) m = fmaxf(m, __shfl_xor_sync(0xffffffffu, m, o));
    __syncthreads();

    float sum = 0.f;
    for (int j = t; j < n4; j += 256) {
        float4 v = row4[j];
        float e0 = __expf(v.x - m), e1 = __expf(v.y - m);
        float e2 = __expf(v.z - m), e3 = __expf(v.w - m);
        sum += (e0 + e1) + (e2 + e3);
        *(__half2*)(rowP + 4 * j)     = __floats2half2_rn(e0, e1);
        *(__half2*)(rowP + 4 * j + 2) = __floats2half2_rn(e2, e3);
    }
    for (int j = (n4 << 2) + t; j < len; j += 256) {
        float e = __expf(row[j] - m);
        rowP[j] = __float2half_rn(e);
        sum += e;
    }
#pragma unroll
    for (int o = 16; o > 0; o >>= 1) sum += __shfl_xor_sync(0xffffffffu, sum, o);
    if (lane == 0) red[w] = sum;
    __syncthreads();
    sum = red[lane & 7];
#pragma unroll
    for (int o = 4; o > 0; o >>= 1) sum += __shfl_xor_sync(0xffffffffu, sum, o);
    if (t == 0) d_inv[b * SEQ + i] = 1.f / sum;

    for (int j = len + t; j < tileEnd; j += 256) rowP[j] = __half(0.f);
}

// ---------------------------------------------------------------------------
// 4) O = P @ V  (NN, k truncated at diagonal; epilogue scales by 1/rowsum)
// ---------------------------------------------------------------------------
__global__ __launch_bounds__(512, 2) void pv_kernel(float* __restrict__ out) {
    extern __shared__ __half smem[];
    __half* sA = smem;
    __half* sB = smem + NSTG * STG_A;

    const int b = blockIdx.z;
    const int m0 = blockIdx.y * 128, n0 = blockIdx.x * 128;
    const int t = threadIdx.x;
    const int wid = t >> 5, lane = t & 31, g = lane >> 2, c = lane & 3;
    const int m_off = (wid >> 2) * 32, n_off = (wid & 3) * 32;

    const unsigned sa_u = (unsigned)__cvta_generic_to_shared(sA) + 2u * ldsm_a_off(m_off, lane);
    const unsigned sb_u = (unsigned)__cvta_generic_to_shared(sB) + 2u * ldsm_bt_off(n_off, lane);

    const __half* gA = d_P + (size_t)b * SEQ * SEQ + (size_t)m0 * SEQ;
    const __half* gB = d_Vh + (size_t)b * SEQ * DIM + n0;
    float* C = out + (size_t)b * SEQ * DIM;

    float acc[2][4][4] = {};
    const int nIter = (m0 + 128) / BK;     // >= 2

    load_km(sA, gA, SEQ, t); load_nm(sB, gB, DIM, t); cp_commit();
    load_km(sA + STG_A, gA + BK, SEQ, t);
    load_nm(sB + STG_B, gB + (size_t)BK * DIM, DIM, t); cp_commit();

    for (int it = 0; it < nIter; ++it) {
        cp_wait1();
        __syncthreads();
        const int pf = it + 2;
        if (pf < nIter) {
            load_km(sA + (pf % 3) * STG_A, gA + pf * BK, SEQ, t);
            load_nm(sB + (pf % 3) * STG_B, gB + (size_t)pf * BK * DIM, DIM, t);
        }
        cp_commit();
        mma_step_NN(sa_u + (unsigned)((it % 3) * STG_A * 2),
                    sb_u + (unsigned)((it % 3) * STG_B * 2), acc);
    }

    const float* inv = d_inv + b * SEQ;
#pragma unroll
    for (int im = 0; im < 2; ++im) {
        const int row = m0 + m_off + im * 16 + g;
        const float i0 = inv[row], i1 = inv[row + 8];
#pragma unroll
        for (int jn = 0; jn < 4; ++jn) {
            const int col = n0 + n_off + jn * 8 + 2 * c;
            *(float2*)(C + (size_t)row * DIM + col) =
                make_float2(acc[im][jn][0] * i0, acc[im][jn][1] * i0);
            *(float2*)(C + (size_t)(row + 8) * DIM + col) =
                make_float2(acc[im][jn][2] * i1, acc[im][jn][3] * i1);
        }
    }
}

extern "C" void kernel_launch(void* const* d_in, const int* in_sizes, int n_in,
                              void* d_out, int out_size) {
    const float* x  = (const float*)d_in[0];
    const float* Wq = (const float*)d_in[1];
    const float* Wk = (const float*)d_in[2];
    const float* Wv = (const float*)d_in[3];
    float* out = (float*)d_out;

    cudaFuncSetAttribute(qkv_kernel,    cudaFuncAttributeMaxDynamicSharedMemorySize, SMEM_NT);
    cudaFuncSetAttribute(scores_kernel, cudaFuncAttributeMaxDynamicSharedMemorySize, SMEM_NT);
    cudaFuncSetAttribute(pv_kernel,     cudaFuncAttributeMaxDynamicSharedMemorySize, SMEM_PV);

    round_x_kernel<<<512, 256>>>((const float4*)x);
    round_w_kernel<<<dim3(64, 1, 3), 256>>>((const float4*)Wq, (const float4*)Wk,
                                            (const float4*)Wv);

    qkv_kernel<<<dim3(DIM / 128, (BATCH * SEQ) / 128, 3), 512, SMEM_NT>>>();
    scores_kernel<<<dim3(SEQ / 128, SEQ / 128, BATCH), 512, SMEM_NT>>>();
    softmax_kernel<<<dim3(SEQ, BATCH), 256>>>();
    pv_kernel<<<dim3(DIM / 128, SEQ / 128, BATCH), 512, SMEM_PV>>>(out);
}